// round 1
// baseline (speedup 1.0000x reference)
#include <cuda_runtime.h>
#include <cuda_bf16.h>

// Problem constants (from reference: MD=4, FAC=1, WSIZE=3)
#define UDIM 9
#define VDIM 9
#define UV   81
#define MD_  4
#define WS_  3
#define HDIM 256
#define WDIM 448
#define HW   (HDIM * WDIM)     // 114688
#define BDIM 4
#define NPIX (BDIM * HW)       // 458752

// 1/log(49), 1/log(81)
#define INV_LOG49 0.25694918f
#define INV_LOG81 0.22755998f

__global__ __launch_bounds__(256) void flow_reg_kernel(
    const float* __restrict__ x, float* __restrict__ out)
{
    int t = blockIdx.x * blockDim.x + threadIdx.x;
    if (t >= NPIX) return;

    int b   = t / HW;
    int pix = t - b * HW;

    const float* xp = x + (long)b * (UV * HW) + pix;

    // ---- load all 81 channel values into registers (coalesced across w) ----
    float xv[UV];
#pragma unroll
    for (int i = 0; i < UV; ++i) {
        xv[i] = __ldg(xp + (long)i * HW);
    }

    // ---- max + argmax (first occurrence; ties measure-zero for float noise) ----
    float m = xv[0];
    int am = 0;
#pragma unroll
    for (int i = 1; i < UV; ++i) {
        if (xv[i] > m) { m = xv[i]; am = i; }
    }
    int iu = am / VDIM;
    int iv = am - iu * VDIM;

    // ---- single exp pass: global sums unconditional, masked sums predicated ----
    float Zg = 0.f, Sg = 0.f;           // global: sum e, sum e*x
    float Zl = 0.f, Sl = 0.f;           // local (masked)
    float Su = 0.f, Sv = 0.f;           // flow numerators
#pragma unroll
    for (int i = 0; i < UV; ++i) {
        const int ui = i / VDIM;        // compile-time per unrolled iter
        const int vi = i - ui * VDIM;
        float e = __expf(xv[i] - m);
        Zg += e;
        Sg = fmaf(e, xv[i], Sg);
        bool in = (iu >= ui - WS_) && (iu <= ui + WS_) &&
                  (iv >= vi - WS_) && (iv <= vi + WS_);
        if (in) {
            Zl += e;
            Sl = fmaf(e, xv[i], Sl);
            Su = fmaf(e, (float)(ui - MD_), Su);
            Sv = fmaf(e, (float)(vi - MD_), Sv);
        }
    }

    // ---- outputs ----
    // entropy identity: -sum p log p = log Z + m - (sum e*x)/Z
    float invZl = __frcp_rn(Zl);
    float invZg = __frcp_rn(Zg);
    float outx  = Su * invZl;
    float outy  = Sv * invZl;
    float lent  = (__logf(Zl) + m - Sl * invZl) * INV_LOG49;
    float gent  = (__logf(Zg) + m - Sg * invZg) * INV_LOG81;

    // flow: (b, 2, h, w), then ent: (b, 2, h, w) appended
    float* flow = out;
    float* ent  = out + (long)BDIM * 2 * HW;
    flow[(long)(b * 2 + 0) * HW + pix] = outx;
    flow[(long)(b * 2 + 1) * HW + pix] = outy;
    ent [(long)(b * 2 + 0) * HW + pix] = lent;
    ent [(long)(b * 2 + 1) * HW + pix] = gent;
}

extern "C" void kernel_launch(void* const* d_in, const int* in_sizes, int n_in,
                              void* d_out, int out_size)
{
    const float* x = (const float*)d_in[0];
    float* out = (float*)d_out;
    dim3 block(256);
    dim3 grid((NPIX + 255) / 256);   // 1792
    flow_reg_kernel<<<grid, block>>>(x, out);
}